// round 14
// baseline (speedup 1.0000x reference)
#include <cuda_runtime.h>
#include <math.h>

#define NN     576
#define MR     144
#define RD     15
#define EDGES  (MR * RD)        // 2160
#define BATCH  256
#define ITERS  3
#define CWPB   2                // codewords per block
#define TPC    288              // threads per codeword (2 per check row)
#define TPB    (CWPB * TPC)     // 576
#define HEDGE  8                // edges per half-thread (uniform; one dummy)
#define MAXDEG 18               // column-degree bound
#define DBLKS  (BATCH / CWPB)   // 128 blocks — single wave, all co-resident

// Per-codeword shared layout (bytes)
#define E_WORDS   (MAXDEG * NN + 8)          // + scratch slot for dummy edge
#define V_WORDS   (NN + 4)                   // + sentinel V[576] = +INF
#define E_SZ      (E_WORDS * 4)
#define V_OFF     E_SZ
#define V_SZ      (V_WORDS * 4)
#define F_OFF     (V_OFF + V_SZ)
#define F_SZ      (NN * 4)
#define CW_SZ     (F_OFF + F_SZ)
#define SMEM_BYTES (CWPB * CW_SZ)            // 92256

#define DUMMY_COL  NN
#define DUMMY_SLOT (MAXDEG * NN)

// Graph structure + intra-launch sync state. Counters are restored to 0 by
// the last-exiting block each call -> identical initial state every call.
__device__ int g_cols[EDGES];
__device__ int g_done = 0;    // blocks that finished their prep share
__device__ int g_exit = 0;    // blocks that finished decode

__device__ __forceinline__ void cw_bar(int half) {
    asm volatile("bar.sync %0, %1;" :: "r"(half + 1), "r"(TPC) : "memory");
}

// ONE kernel, ONE wave (128 blocks <= 148 SMs, all co-resident -> the
// g_done gate cannot deadlock). Each block first ballot-compacts its share
// of H rows (rows bid and bid+128), then decodes 2 codewords.
__global__ __launch_bounds__(TPB, 1)
void ldpc_fused(const float* __restrict__ H,
                const float* __restrict__ r,
                const float* __restrict__ alpha,
                const float* __restrict__ beta,
                float* __restrict__ out) {
    extern __shared__ char sm[];
    __shared__ int woff[18];

    const int t    = threadIdx.x;
    const int half = t / TPC;             // codeword slot in this block
    const int u    = t - half * TPC;      // 0..287 within codeword
    const int row  = u >> 1;              // 0..143
    const int hf   = u & 1;               // edge-split half
    const int b    = blockIdx.x * CWPB + half;

    float* E_sh = (float*)(sm + half * CW_SZ);
    float* V    = (float*)(sm + half * CW_SZ + V_OFF);
    int*   fill = (int*)  (sm + half * CW_SZ + F_OFF);

    // Issue the r loads early (independent of prep).
    const int n0 = u, n1 = u + TPC;
    const float rc0 = r[b * NN + n0];
    const float rc1 = r[b * NN + n1];

    float a_[ITERS], bt_[ITERS];
    #pragma unroll
    for (int it = 0; it < ITERS; it++) { a_[it] = alpha[it]; bt_[it] = beta[it]; }

    // ---- distributed prep: this block handles H rows {bid, bid+128} ----
    const int w = t >> 5, l = t & 31;
    for (int m = blockIdx.x; m < MR; m += DBLKS) {
        const float v = H[m * NN + t];
        const unsigned mask = __ballot_sync(0xFFFFFFFFu, v == 1.0f);
        if (l == 0) woff[w] = __popc(mask);
        __syncthreads();
        if (w == 0) {
            int orig = (l < 18) ? woff[l] : 0;
            int c = orig;
            #pragma unroll
            for (int off = 1; off < 32; off <<= 1) {
                int x = __shfl_up_sync(0xFFFFFFFFu, c, off);
                if (l >= off) c += x;
            }
            if (l < 18) woff[l] = c - orig;   // exclusive prefix
        }
        __syncthreads();
        if (v == 1.0f) {
            int pos = woff[w] + __popc(mask & ((1u << l) - 1u));
            g_cols[m * RD + pos] = t;
        }
        __syncthreads();   // woff reusable next pass
    }
    __threadfence();       // release g_cols writes
    __syncthreads();
    if (t == 0) atomicAdd(&g_done, 1);

    // ---- local init while other blocks finish prep ----
    V[n0] = rc0;  V[n1] = rc1;
    fill[n0] = 0; fill[n1] = 0;
    if (u == 0) V[DUMMY_COL] = INFINITY;   // sentinel for dummy edges

    // ---- gate: all 128 blocks' prep shares published (acquire) ----
    if (t == 0) {
        while (atomicAdd(&g_done, 0) < DBLKS) __nanosleep(32);
        __threadfence();
    }
    __syncthreads();

    // This half's edges: real j = hf*8 + jj for jj < ne; hf=1's jj=7 is dummy.
    const int j0 = hf * HEDGE;                 // 0 or 8
    const int ne = hf ? (RD - HEDGE) : HEDGE;  // 7 or 8 real edges
    int cols[HEDGE];
    #pragma unroll
    for (int jj = 0; jj < HEDGE; jj++)
        cols[jj] = (jj < ne) ? g_cols[row * RD + j0 + jj] : DUMMY_COL;

    // One-time slot assignment (unique slot within each column; dummy->scratch).
    int slot[HEDGE];
    #pragma unroll
    for (int jj = 0; jj < HEDGE; jj++) {
        if (jj < ne) {
            int q = atomicAdd(&fill[cols[jj]], 1);
            slot[jj] = q * NN + cols[jj];
        } else {
            slot[jj] = DUMMY_SLOT;
        }
    }
    cw_bar(half);   // slots + degrees final

    const int cd0 = fill[n0], cd1 = fill[n1];

    float Eprev[HEDGE];
    #pragma unroll
    for (int jj = 0; jj < HEDGE; jj++) Eprev[jj] = 0.0f;

    #pragma unroll
    for (int it = 0; it < ITERS; it++) {
        const float a  = a_[it];
        const float bt = bt_[it];

        // ---- row phase: gather, sign XOR, min1/min2 (uniform 8 edges) ----
        float am[HEDGE];
        unsigned sb[HEDGE];
        unsigned sgn = 0u;
        #pragma unroll
        for (int jj = 0; jj < HEDGE; jj++) {
            float m = V[cols[jj]] - Eprev[jj];
            sb[jj] = __float_as_uint(m) & 0x80000000u;
            sgn   ^= sb[jj];
            am[jj] = fabsf(m);
        }
        // two sub-chains of 4 + merge (first-index tie-break)
        float a1 = INFINITY, a2 = INFINITY; int ja = j0;
        #pragma unroll
        for (int jj = 0; jj < 4; jj++) {
            if (am[jj] < a1) { a2 = a1; a1 = am[jj]; ja = j0 + jj; }
            else if (am[jj] < a2) { a2 = am[jj]; }
        }
        float b1 = INFINITY, b2 = INFINITY; int jb = j0 + 4;
        #pragma unroll
        for (int jj = 4; jj < HEDGE; jj++) {
            if (am[jj] < b1) { b2 = b1; b1 = am[jj]; jb = j0 + jj; }
            else if (am[jj] < b2) { b2 = am[jj]; }
        }
        const bool  tA = (a1 <= b1);
        float min1 = tA ? a1 : b1;
        float min2 = tA ? fminf(a2, b1) : fminf(b2, a1);
        int   jmin = tA ? ja : jb;

        // ---- cross-half merge via 3 shfl_xor(1): sign bit packed in jmin ----
        const int js = (jmin << 1) | (int)(sgn >> 31);
        const float o1 = __shfl_xor_sync(0xFFFFFFFFu, min1, 1);
        const float o2 = __shfl_xor_sync(0xFFFFFFFFu, min2, 1);
        const int   ojs = __shfl_xor_sync(0xFFFFFFFFu, js, 1);
        const unsigned sgc = sgn ^ ((unsigned)ojs << 31);
        const bool mine = hf ? (min1 < o1) : (min1 <= o1);   // low index wins ties
        const int   jminc = mine ? jmin : (ojs >> 1);
        const float min1c = mine ? min1 : o1;
        const float min2c = mine ? fminf(min2, o1) : fminf(o2, min1);

        const float mag1 = a * fmaxf(0.0f, min1c - bt);
        const float mag2 = a * fmaxf(0.0f, min2c - bt);

        // ---- emit (uniform 8; dummy writes scratch slot, value unused) ----
        #pragma unroll
        for (int jj = 0; jj < HEDGE; jj++) {
            float mag = ((j0 + jj) == jminc) ? mag2 : mag1;
            float e = __uint_as_float(__float_as_uint(mag) ^ (sgc ^ sb[jj]));
            Eprev[jj] = e;
            E_sh[slot[jj]] = e;
        }
        cw_bar(half);   // edges published; V reads done

        // ---- column phase: 2 owned columns, conflict-free ----
        float s0 = rc0, s1 = rc1;
        for (int q = 0; q < cd0; q++) s0 += E_sh[q * NN + n0];
        for (int q = 0; q < cd1; q++) s1 += E_sh[q * NN + n1];
        if (it < ITERS - 1) {
            V[n0] = s0;
            V[n1] = s1;
            cw_bar(half);
        } else {
            out[b * NN + n0] = s0;   // coalesced
            out[b * NN + n1] = s1;
        }
    }

    // Reset sync state: last block zeroes both counters so the next call /
    // graph replay starts from the identical state.
    __syncthreads();
    if (t == 0) {
        int v = atomicAdd(&g_exit, 1);
        if (v == DBLKS - 1) {
            atomicExch(&g_exit, 0);
            atomicExch(&g_done, 0);
        }
    }
}

extern "C" void kernel_launch(void* const* d_in, const int* in_sizes, int n_in,
                              void* d_out, int out_size) {
    const float* r     = (const float*)d_in[0];   // (256, 576)
    const float* H     = (const float*)d_in[1];   // (144, 576)
    const float* alpha = (const float*)d_in[2];   // (3,)
    const float* beta  = (const float*)d_in[3];   // (3,)
    float* out = (float*)d_out;                   // (256, 576)

    cudaFuncSetAttribute(ldpc_fused,
                         cudaFuncAttributeMaxDynamicSharedMemorySize, SMEM_BYTES);

    ldpc_fused<<<DBLKS, TPB, SMEM_BYTES>>>(H, r, alpha, beta, out);
}

// round 15
// speedup vs baseline: 1.2216x; 1.2216x over previous
#include <cuda_runtime.h>
#include <math.h>

#define NN     576
#define MR     144
#define RD     15
#define EDGES  (MR * RD)        // 2160
#define BATCH  256
#define ITERS  3
#define CWPB   2                // codewords per block
#define TPC    288              // threads per codeword (2 per check row)
#define TPB    (CWPB * TPC)     // 576
#define HEDGE  8                // edges per half-thread (uniform; one dummy)
#define MAXDEG 18               // column-degree bound
#define DBLKS  (BATCH / CWPB)   // 128

// Per-codeword shared layout (bytes)
#define E_WORDS   (MAXDEG * NN + 8)          // + scratch slot for dummy edge
#define V_WORDS   (NN + 4)                   // + sentinel V[576] = +INF
#define E_SZ      (E_WORDS * 4)
#define V_OFF     E_SZ
#define V_SZ      (V_WORDS * 4)
#define F_OFF     (V_OFF + V_SZ)
#define F_SZ      (NN * 4)
#define CW_SZ     (F_OFF + F_SZ)
#define SMEM_BYTES (CWPB * CW_SZ)            // 92256

#define DUMMY_COL  NN
#define DUMMY_SLOT (MAXDEG * NN)

// Column indices of the 15 ones in each of the 144 rows of H.
__device__ int g_cols[EDGES];

// Prep: one block per row, 576 threads, one coalesced load each.
// Signals programmatic launch completion as soon as g_cols is published,
// releasing the PDL-gated decode kernel early.
__global__ void ldpc_prep(const float* __restrict__ H) {
    __shared__ int woff[18];
    const int m = blockIdx.x;
    const int t = threadIdx.x;
    const int w = t >> 5, l = t & 31;

    const float v = H[m * NN + t];
    const unsigned mask = __ballot_sync(0xFFFFFFFFu, v == 1.0f);
    if (l == 0) woff[w] = __popc(mask);
    __syncthreads();
    if (w == 0) {
        int orig = (l < 18) ? woff[l] : 0;
        int c = orig;
        #pragma unroll
        for (int off = 1; off < 32; off <<= 1) {
            int x = __shfl_up_sync(0xFFFFFFFFu, c, off);
            if (l >= off) c += x;
        }
        if (l < 18) woff[l] = c - orig;   // exclusive prefix
    }
    __syncthreads();
    if (v == 1.0f) {
        int pos = woff[w] + __popc(mask & ((1u << l) - 1u));
        g_cols[m * RD + pos] = t;
    }
    __syncthreads();
    cudaTriggerProgrammaticLaunchCompletion();
}

__device__ __forceinline__ void cw_bar(int half) {
    asm volatile("bar.sync %0, %1;" :: "r"(half + 1), "r"(TPC) : "memory");
}

// Decode: one block = TWO independent codewords (576 threads, 288 each).
// Launched with PDL: CTAs roll out and run all prep-independent setup while
// ldpc_prep is still executing; cudaGridDependencySynchronize() gates only
// the g_cols reads. Decode body: 2 threads/check row, uniform 8 edges
// (dummy -> V[576]=+INF), 3-value shfl merge, 2 owned columns, named barriers.
__global__ __launch_bounds__(TPB, 1)
void ldpc_decode_kernel(const float* __restrict__ r,
                        const float* __restrict__ alpha,
                        const float* __restrict__ beta,
                        float* __restrict__ out) {
    extern __shared__ char sm[];

    const int t    = threadIdx.x;
    const int half = t / TPC;             // codeword slot in this block
    const int u    = t - half * TPC;      // 0..287 within codeword
    const int row  = u >> 1;              // 0..143
    const int hf   = u & 1;               // edge-split half
    const int b    = blockIdx.x * CWPB + half;

    float* E_sh = (float*)(sm + half * CW_SZ);
    float* V    = (float*)(sm + half * CW_SZ + V_OFF);
    int*   fill = (int*)  (sm + half * CW_SZ + F_OFF);

    // ---- prep-independent setup (overlaps with ldpc_prep via PDL) ----
    float a_[ITERS], bt_[ITERS];
    #pragma unroll
    for (int it = 0; it < ITERS; it++) { a_[it] = alpha[it]; bt_[it] = beta[it]; }

    const int n0 = u, n1 = u + TPC;       // owned columns (coalesced)
    const float rc0 = r[b * NN + n0];
    const float rc1 = r[b * NN + n1];
    V[n0] = rc0;  V[n1] = rc1;
    fill[n0] = 0; fill[n1] = 0;
    if (u == 0) V[DUMMY_COL] = INFINITY;  // sentinel for dummy edges
    cw_bar(half);                          // V + fill ready

    // ---- gate on prep completion, then read the graph ----
    cudaGridDependencySynchronize();

    const int j0 = hf * HEDGE;                 // 0 or 8
    const int ne = hf ? (RD - HEDGE) : HEDGE;  // 7 or 8 real edges
    int cols[HEDGE];
    #pragma unroll
    for (int jj = 0; jj < HEDGE; jj++)
        cols[jj] = (jj < ne) ? g_cols[row * RD + j0 + jj] : DUMMY_COL;

    // One-time slot assignment (unique slot within each column; dummy->scratch).
    int slot[HEDGE];
    #pragma unroll
    for (int jj = 0; jj < HEDGE; jj++) {
        if (jj < ne) {
            int q = atomicAdd(&fill[cols[jj]], 1);
            slot[jj] = q * NN + cols[jj];
        } else {
            slot[jj] = DUMMY_SLOT;
        }
    }
    cw_bar(half);   // slots + degrees final

    const int cd0 = fill[n0], cd1 = fill[n1];

    float Eprev[HEDGE];
    #pragma unroll
    for (int jj = 0; jj < HEDGE; jj++) Eprev[jj] = 0.0f;

    #pragma unroll
    for (int it = 0; it < ITERS; it++) {
        const float a  = a_[it];
        const float bt = bt_[it];

        // ---- row phase: gather, sign XOR, min1/min2 (uniform 8 edges) ----
        float am[HEDGE];
        unsigned sb[HEDGE];
        unsigned sgn = 0u;
        #pragma unroll
        for (int jj = 0; jj < HEDGE; jj++) {
            float m = V[cols[jj]] - Eprev[jj];
            sb[jj] = __float_as_uint(m) & 0x80000000u;
            sgn   ^= sb[jj];
            am[jj] = fabsf(m);
        }
        // two sub-chains of 4 + merge (first-index tie-break)
        float a1 = INFINITY, a2 = INFINITY; int ja = j0;
        #pragma unroll
        for (int jj = 0; jj < 4; jj++) {
            if (am[jj] < a1) { a2 = a1; a1 = am[jj]; ja = j0 + jj; }
            else if (am[jj] < a2) { a2 = am[jj]; }
        }
        float b1 = INFINITY, b2 = INFINITY; int jb = j0 + 4;
        #pragma unroll
        for (int jj = 4; jj < HEDGE; jj++) {
            if (am[jj] < b1) { b2 = b1; b1 = am[jj]; jb = j0 + jj; }
            else if (am[jj] < b2) { b2 = am[jj]; }
        }
        const bool  tA = (a1 <= b1);
        float min1 = tA ? a1 : b1;
        float min2 = tA ? fminf(a2, b1) : fminf(b2, a1);
        int   jmin = tA ? ja : jb;

        // ---- cross-half merge via 3 shfl_xor(1): sign bit packed in jmin ----
        const int js = (jmin << 1) | (int)(sgn >> 31);
        const float o1 = __shfl_xor_sync(0xFFFFFFFFu, min1, 1);
        const float o2 = __shfl_xor_sync(0xFFFFFFFFu, min2, 1);
        const int   ojs = __shfl_xor_sync(0xFFFFFFFFu, js, 1);
        const unsigned sgc = sgn ^ ((unsigned)ojs << 31);
        const bool mine = hf ? (min1 < o1) : (min1 <= o1);   // low index wins ties
        const int   jminc = mine ? jmin : (ojs >> 1);
        const float min1c = mine ? min1 : o1;
        const float min2c = mine ? fminf(min2, o1) : fminf(o2, min1);

        const float mag1 = a * fmaxf(0.0f, min1c - bt);
        const float mag2 = a * fmaxf(0.0f, min2c - bt);

        // ---- emit (uniform 8; dummy writes scratch slot, value unused) ----
        #pragma unroll
        for (int jj = 0; jj < HEDGE; jj++) {
            float mag = ((j0 + jj) == jminc) ? mag2 : mag1;
            float e = __uint_as_float(__float_as_uint(mag) ^ (sgc ^ sb[jj]));
            Eprev[jj] = e;
            E_sh[slot[jj]] = e;
        }
        cw_bar(half);   // edges published; V reads done

        // ---- column phase: 2 owned columns, conflict-free ----
        float s0 = rc0, s1 = rc1;
        for (int q = 0; q < cd0; q++) s0 += E_sh[q * NN + n0];
        for (int q = 0; q < cd1; q++) s1 += E_sh[q * NN + n1];
        if (it < ITERS - 1) {
            V[n0] = s0;
            V[n1] = s1;
            cw_bar(half);
        } else {
            out[b * NN + n0] = s0;   // coalesced
            out[b * NN + n1] = s1;
        }
    }
}

extern "C" void kernel_launch(void* const* d_in, const int* in_sizes, int n_in,
                              void* d_out, int out_size) {
    const float* r     = (const float*)d_in[0];   // (256, 576)
    const float* H     = (const float*)d_in[1];   // (144, 576)
    const float* alpha = (const float*)d_in[2];   // (3,)
    const float* beta  = (const float*)d_in[3];   // (3,)
    float* out = (float*)d_out;                   // (256, 576)

    cudaFuncSetAttribute(ldpc_decode_kernel,
                         cudaFuncAttributeMaxDynamicSharedMemorySize, SMEM_BYTES);

    // Primary kernel: graph prep.
    ldpc_prep<<<MR, NN>>>(H);

    // Secondary kernel with Programmatic Dependent Launch: its CTAs may start
    // (and run all prep-independent setup) while ldpc_prep is still running;
    // cudaGridDependencySynchronize() inside gates the g_cols consumption.
    cudaLaunchConfig_t cfg = {};
    cfg.gridDim  = dim3(DBLKS);
    cfg.blockDim = dim3(TPB);
    cfg.dynamicSmemBytes = SMEM_BYTES;
    cfg.stream = 0;
    cudaLaunchAttribute attrs[1];
    attrs[0].id = cudaLaunchAttributeProgrammaticStreamSerialization;
    attrs[0].val.programmaticStreamSerializationAllowed = 1;
    cfg.attrs = attrs;
    cfg.numAttrs = 1;
    cudaLaunchKernelEx(&cfg, ldpc_decode_kernel, r, alpha, beta, out);
}